// round 5
// baseline (speedup 1.0000x reference)
#include <cuda_runtime.h>
#include <cstddef>

#define K_DIM 2048
#define M_DIM 512
#define N_DIM 64
#define EPS_F 1e-8f

#define P_BLOCKS   128   // producers, 16 rows each
#define H_BLOCKS   4     // hard blocks
#define C_BLOCKS   148   // dedicated consumers
#define GRID_TOTAL (P_BLOCKS + H_BLOCKS + C_BLOCKS)  // 280
#define P_ROWS     16
#define CB_ROWS    4     // rows per chunk/pass
#define N_CHUNKS   (K_DIM / CB_ROWS)  // 512

// ---- device scratch (allowed: __device__ globals) ----
__device__ unsigned g_flag[N_CHUNKS];
__device__ unsigned g_ctr;
__device__ unsigned g_hard;

__global__ void reset_kernel() {
    if (threadIdx.x < N_CHUNKS) g_flag[threadIdx.x] = 0u;
    if (threadIdx.x == 0) { g_ctr = 0u; g_hard = 0u; }
}

__device__ __forceinline__ unsigned ld_acq(const unsigned* p) {
    unsigned v;
    asm volatile("ld.acquire.gpu.u32 %0, [%1];" : "=r"(v) : "l"(p) : "memory");
    return v;
}

// ---------------------------------------------------------------------------
// One gemm+softmax pass over CB_ROWS=4 rows (rows already in sh[row_sh0..]).
// FFMA2 even/odd-i packed accumulate, w_att prefetch double-buffered.
// ---------------------------------------------------------------------------
__device__ __forceinline__ void produce_pass(
    const float* __restrict__ w_att, float* __restrict__ soft_out,
    const float* sh, float* red, int row_sh0, int k_glob0,
    int tid, int lane, int wid)
{
    unsigned long long acc2[CB_ROWS];
#pragma unroll
    for (int r = 0; r < CB_ROWS; r++) acc2[r] = 0ULL;

    const int j = tid;
    float w0 = w_att[0 * M_DIM + j];
    float w1 = w_att[1 * M_DIM + j];
    float w2 = w_att[2 * M_DIM + j];
    float w3 = w_att[3 * M_DIM + j];

    for (int i = 0; i < M_DIM; i += 4) {
        int ip = (i + 4) & (M_DIM - 1);   // wrap prefetch (harmless, L1-hot)
        float nw0 = w_att[(size_t)(ip + 0) * M_DIM + j];
        float nw1 = w_att[(size_t)(ip + 1) * M_DIM + j];
        float nw2 = w_att[(size_t)(ip + 2) * M_DIM + j];
        float nw3 = w_att[(size_t)(ip + 3) * M_DIM + j];

        unsigned long long wp0, wp1;
        asm("mov.b64 %0, {%1, %2};" : "=l"(wp0) : "f"(w0), "f"(w1));
        asm("mov.b64 %0, {%1, %2};" : "=l"(wp1) : "f"(w2), "f"(w3));
#pragma unroll
        for (int r = 0; r < CB_ROWS; r++) {
            ulonglong2 xp = *(const ulonglong2*)&sh[(row_sh0 + r) * M_DIM + i];
            asm("fma.rn.f32x2 %0, %1, %2, %0;" : "+l"(acc2[r]) : "l"(xp.x), "l"(wp0));
            asm("fma.rn.f32x2 %0, %1, %2, %0;" : "+l"(acc2[r]) : "l"(xp.y), "l"(wp1));
        }
        w0 = nw0; w1 = nw1; w2 = nw2; w3 = nw3;
    }

    float acc[CB_ROWS];
#pragma unroll
    for (int r = 0; r < CB_ROWS; r++) {
        float lo, hi;
        asm("mov.b64 {%0, %1}, %2;" : "=f"(lo), "=f"(hi) : "l"(acc2[r]));
        acc[r] = lo + hi;
    }

#pragma unroll 1
    for (int r = 0; r < CB_ROWS; r++) {
        float v = acc[r];
#pragma unroll
        for (int o = 16; o; o >>= 1)
            v = fmaxf(v, __shfl_xor_sync(0xffffffffu, v, o));
        if (lane == 0) red[wid] = v;
        __syncthreads();
        if (tid < 32) {
            float w = (lane < 16) ? red[lane] : -3.402823466e38f;
#pragma unroll
            for (int o = 8; o; o >>= 1)
                w = fmaxf(w, __shfl_xor_sync(0xffffffffu, w, o));
            if (lane == 0) red[16] = w;
        }
        __syncthreads();
        float rowmax = red[16];

        float e = __expf(acc[r] - rowmax);

        v = e;
#pragma unroll
        for (int o = 16; o; o >>= 1)
            v += __shfl_xor_sync(0xffffffffu, v, o);
        if (lane == 0) red[wid] = v;
        __syncthreads();
        if (tid < 32) {
            float w = (lane < 16) ? red[lane] : 0.0f;
#pragma unroll
            for (int o = 8; o; o >>= 1)
                w += __shfl_xor_sync(0xffffffffu, w, o);
            if (lane == 0) red[16] = w;
        }
        __syncthreads();

        soft_out[(size_t)(k_glob0 + r) * M_DIM + j] = e / red[16] + EPS_F;
        __syncthreads();
    }
}

// ---------------------------------------------------------------------------
// Main kernel: producers (gemm+softmax, flag per 4-row chunk), hard blocks,
// then everyone becomes a consumer streaming mask/out stores.
// ---------------------------------------------------------------------------
__global__ __launch_bounds__(512, 2)
void fused_overlap_kernel(const float* __restrict__ x,
                          const float* __restrict__ w_att,
                          const float* __restrict__ w_b,
                          float* __restrict__ out,
                          float* __restrict__ hard,
                          float* __restrict__ soft,
                          float* __restrict__ mask) {
    __shared__ __align__(16) float sh[P_ROWS * M_DIM];  // 32 KB, reused
    __shared__ float red[17];
    __shared__ unsigned f_sh;

    const int tid  = threadIdx.x;
    const int lane = tid & 31;
    const int wid  = tid >> 5;
    const int bid  = blockIdx.x;

    if (bid < P_BLOCKS) {
        // ---------------- producer ----------------
        const int kb = bid * P_ROWS;
        for (int e = tid; e < P_ROWS * M_DIM; e += 512) {
            int r = e >> 9;
            int m = e & (M_DIM - 1);
            sh[e] = x[(size_t)(kb + r) * M_DIM + m];
        }
        __syncthreads();

#pragma unroll 1
        for (int b = 0; b < P_ROWS / CB_ROWS; b++) {
            produce_pass(w_att, soft, sh, red, b * CB_ROWS, kb + b * CB_ROWS,
                         tid, lane, wid);
            __syncthreads();
            if (tid == 0) {
                __threadfence();
                atomicExch(&g_flag[b * P_BLOCKS + bid], 1u);  // b-major order
            }
        }
    } else if (bid < P_BLOCKS + H_BLOCKS) {
        // ---------------- hard: warp per column n ----------------
        const int n = (bid - P_BLOCKS) * 16 + wid;  // 0..63

        float v[16];
#pragma unroll
        for (int jj = 0; jj < 16; jj++)
            v[jj] = w_b[(lane + 32 * jj) * N_DIM + n];

        float t[8];
#pragma unroll
        for (int i = 0; i < 8; i++) t[i] = -3.402823466e38f;
#pragma unroll
        for (int jj = 0; jj < 16; jj++) {
            float val = v[jj];
            if (val > t[7]) {
                t[7] = val;
#pragma unroll
                for (int i = 7; i > 0; i--) {
                    if (t[i] > t[i - 1]) {
                        float tmp = t[i - 1]; t[i - 1] = t[i]; t[i] = tmp;
                    }
                }
            }
        }

        float thr = 0.0f;
#pragma unroll
        for (int it = 0; it < 8; it++) {
            float m = t[0];
#pragma unroll
            for (int o = 16; o; o >>= 1)
                m = fmaxf(m, __shfl_xor_sync(0xffffffffu, m, o));
            unsigned bal = __ballot_sync(0xffffffffu, t[0] == m);
            int src = __ffs(bal) - 1;
            if (lane == src) {
#pragma unroll
                for (int i = 0; i < 7; i++) t[i] = t[i + 1];
                t[7] = -3.402823466e38f;
            }
            thr = m;
        }

#pragma unroll
        for (int jj = 0; jj < 16; jj++) {
            float shv = v[jj] - thr + EPS_F;
            shv = fminf(fmaxf(shv, -1.0f), 1.0f);
            hard[(lane + 32 * jj) * N_DIM + n] = (shv + 1.0f) * 0.5f;
        }
        __syncthreads();
        if (tid == 0) {
            __threadfence();
            atomicAdd(&g_hard, 1u);
        }
    }

    // ---------------- consumer phase (all blocks) ----------------
    if (tid == 0) {
        while (ld_acq(&g_hard) < (unsigned)H_BLOCKS) __nanosleep(64);
    }
    __syncthreads();

    const float4* h4 = (const float4*)hard;

    while (true) {
        if (tid == 0) f_sh = atomicAdd(&g_ctr, 1u);
        __syncthreads();
        unsigned f = f_sh;
        if (f >= (unsigned)N_CHUNKS) break;

        if (tid == 0) {
            while (ld_acq(&g_flag[f]) == 0u) __nanosleep(64);
        }
        __syncthreads();

        const int p  = f & (P_BLOCKS - 1);
        const int b  = f >> 7;
        const int k0 = p * P_ROWS + b * CB_ROWS;

        // stage soft & soft*x for 4 rows into shared
        for (int t = tid; t < CB_ROWS * M_DIM; t += 512) {
            int r = t >> 9;
            int m = t & (M_DIM - 1);
            float s  = soft[(size_t)(k0 + r) * M_DIM + m];
            float xv = x[(size_t)(k0 + r) * M_DIM + m];
            sh[t]                    = s;
            sh[CB_ROWS * M_DIM + t]  = s * xv;
        }
        __syncthreads();

        float4* o4 = (float4*)out  + (size_t)k0 * (M_DIM * N_DIM / 4);
        float4* m4 = (float4*)mask + (size_t)k0 * (M_DIM * N_DIM / 4);

#pragma unroll 8
        for (int e = tid; e < CB_ROWS * M_DIM * (N_DIM / 4); e += 512) {
            int inner = e & (M_DIM * N_DIM / 4 - 1);  // within-row-block idx
            int r = e >> 13;
            int m = inner >> 4;
            float4 h = h4[inner];
            float s  = sh[r * M_DIM + m];
            float pp = sh[CB_ROWS * M_DIM + r * M_DIM + m];

            float4 mw, o;
            mw.x = h.x * s;  mw.y = h.y * s;  mw.z = h.z * s;  mw.w = h.w * s;
            o.x  = h.x * pp; o.y  = h.y * pp; o.z  = h.z * pp; o.w  = h.w * pp;

            __stcs(&m4[e], mw);
            __stcs(&o4[e], o);
        }
        __syncthreads();  // sh reused next chunk
    }
}

// ---------------------------------------------------------------------------
// d_out layout (reference return order):
//   out         [K,M,N] : offset 0           (67,108,864)
//   scores_hard [M,N]   : offset 67,108,864  (32,768)
//   scores_soft [K,M]   : offset 67,141,632  (1,048,576)
//   mask_weight [K,M,N] : offset 68,190,208  (67,108,864)
// ---------------------------------------------------------------------------
extern "C" void kernel_launch(void* const* d_in, const int* in_sizes, int n_in,
                              void* d_out, int out_size) {
    const float* x     = (const float*)d_in[0];
    const float* w_att = (const float*)d_in[1];
    const float* w_b   = (const float*)d_in[2];

    float* out  = (float*)d_out;
    float* hard = out + 67108864ULL;
    float* soft = out + 67141632ULL;
    float* mask = out + 68190208ULL;

    reset_kernel<<<1, 512>>>();
    fused_overlap_kernel<<<GRID_TOTAL, 512>>>(x, w_att, w_b, out, hard, soft, mask);
}